// round 17
// baseline (speedup 1.0000x reference)
#include <cuda_runtime.h>
#include <cuda_bf16.h>
#include <mma.h>
#include <math.h>

using namespace nvcuda;

#define N_NODES  100000
#define N_EDGES  1600000
#define N_GRAPHS 2048
#define CAP      96          // padded per-node bucket capacity (deg: mean 16, sigma 4)

// ---------------- scratch (device globals; no allocations allowed) ----------
__device__ int   g_cursor[N_NODES];              // bump counters -> in-degree
__device__ int   g_srcs[(size_t)N_NODES * CAP];  // padded per-node src buckets
__device__ float g_dinv[N_NODES];
__device__ float g_A[(size_t)N_NODES * 128];     // h_scaled = (X@W) * dinv[row]
__device__ float g_B[(size_t)N_NODES * 128];     // aggregated output / next input
__device__ float g_pool[N_GRAPHS * 32];

// ---------------- helpers ----------------------------------------------------
__device__ __forceinline__ void red_add_f32x4(float* addr, float4 v) {
    asm volatile("red.global.add.v4.f32 [%0], {%1,%2,%3,%4};"
                 :: "l"(addr), "f"(v.x), "f"(v.y), "f"(v.z), "f"(v.w)
                 : "memory");
}
__device__ __forceinline__ void acc4(float4& a, float4 m) {
    a.x += m.x; a.y += m.y; a.z += m.z; a.w += m.w;
}

// ---------------- setup kernels -----------------------------------------------
__global__ void zero_kernel(float* loss_slot) {
    int i = blockIdx.x * blockDim.x + threadIdx.x;
    if (i < N_NODES)       g_cursor[i] = 0;
    if (i < N_GRAPHS * 32) g_pool[i]   = 0.f;
    if (i == 0 && loss_slot) *loss_slot = 0.f;
}

// bump-allocate into padded per-node buckets; 4 edges per thread (int4 loads,
// 4 independent atomics in flight — fill was atomic-latency-bound at issue=4%)
__global__ void fill_kernel(const int* __restrict__ src, const int* __restrict__ dst) {
    int e = (blockIdx.x * blockDim.x + threadIdx.x) * 4;
    if (e + 3 < N_EDGES) {
        int4 d4 = __ldg((const int4*)(dst + e));
        int4 s4 = __ldg((const int4*)(src + e));
        int p0 = atomicAdd(&g_cursor[d4.x], 1);
        int p1 = atomicAdd(&g_cursor[d4.y], 1);
        int p2 = atomicAdd(&g_cursor[d4.z], 1);
        int p3 = atomicAdd(&g_cursor[d4.w], 1);
        if (p0 < CAP) g_srcs[(size_t)d4.x * CAP + p0] = s4.x;
        if (p1 < CAP) g_srcs[(size_t)d4.y * CAP + p1] = s4.y;
        if (p2 < CAP) g_srcs[(size_t)d4.z * CAP + p2] = s4.z;
        if (p3 < CAP) g_srcs[(size_t)d4.w * CAP + p3] = s4.w;
    } else {
        for (; e < N_EDGES; e++) {
            int d = __ldg(&dst[e]);
            int p = atomicAdd(&g_cursor[d], 1);
            if (p < CAP) g_srcs[(size_t)d * CAP + p] = __ldg(&src[e]);
        }
    }
}

__global__ void dinv_kernel() {
    int i = blockIdx.x * blockDim.x + threadIdx.x;
    if (i < N_NODES) g_dinv[i] = rsqrtf((float)g_cursor[i] + 1.0f);
}

// ---------------- GEMM via bf16 tensor cores (m16n16k16) ----------------------
// HS[row,:] = (relu?(X[row,:]) * dinv[row]) @ W   (dinv folded into staged X)
// X and W converted to bf16 once at staging; B fragments hoisted to registers;
// next tile's X prefetched during mma; strips interleaved (independent chains).
template<int K, int M, bool RELU_IN, int ROWS>
__global__ void __launch_bounds__(256, 2)
gcn_gemm_tc(const float* __restrict__ X, const float* __restrict__ W,
            float* __restrict__ HS) {
    constexpr int XSTR   = K + 16;              // bf16 elements (32B pad)
    constexpr int NTILE  = M / 16;              // column tiles (8 / 4 / 2)
    constexpr int RGRP   = 8 / NTILE;           // row groups
    constexpr int STRIPS = ROWS / 16 / RGRP;    // 16-row strips per warp
    constexpr int KS     = K / 16;              // k-steps (bf16: 16 per mma)
    constexpr int PREN   = ROWS * (K / 4) / 256;  // float4 prefetches per thread
    static_assert(STRIPS >= 1, "ROWS too small for RGRP");
    extern __shared__ __nv_bfloat16 smem_b[];
    __nv_bfloat16* Ws = smem_b;                  // K*M bf16
    __nv_bfloat16* Xs = smem_b + K * M;          // ROWS * XSTR bf16

    for (int i = threadIdx.x; i < K * M / 4; i += 256) {
        float4 w = __ldg((const float4*)W + i);
        __nv_bfloat162 lo = __floats2bfloat162_rn(w.x, w.y);
        __nv_bfloat162 hi = __floats2bfloat162_rn(w.z, w.w);
        uint2 u;
        u.x = *(unsigned*)&lo;
        u.y = *(unsigned*)&hi;
        *(uint2*)(Ws + i * 4) = u;
    }
    __syncthreads();

    const int warp = threadIdx.x >> 5;
    const int tile = warp % NTILE;
    const int rg   = warp / NTILE;

    // hoist B fragments: load once (bf16, no further conversion)
    wmma::fragment<wmma::matrix_b, 16, 16, 16, __nv_bfloat16,
                   wmma::row_major> bf[KS];
    #pragma unroll
    for (int ks = 0; ks < KS; ks++)
        wmma::load_matrix_sync(bf[ks], Ws + ks * 16 * M + tile * 16, M);

    // register prefetch buffers (X values + per-row dinv)
    float4 pre[PREN];
    float  pdi[PREN];

    auto prefetch = [&](int r0) {
        #pragma unroll
        for (int p = 0; p < PREN; p++) {
            int i  = threadIdx.x + p * 256;
            int rr = i / (K / 4), kk = i % (K / 4);
            int row = r0 + rr;
            if (row < N_NODES) {
                pre[p] = __ldg((const float4*)(X + (size_t)row * K) + kk);
                pdi[p] = __ldg(&g_dinv[row]);
            } else {
                pre[p] = make_float4(0.f, 0.f, 0.f, 0.f);
                pdi[p] = 0.f;
            }
        }
    };

    int row0 = blockIdx.x * ROWS;
    if (row0 < N_NODES) prefetch(row0);

    for (; row0 < N_NODES; row0 += gridDim.x * ROWS) {
        __syncthreads();   // previous tile's compute done reading Xs
        #pragma unroll
        for (int p = 0; p < PREN; p++) {
            int i  = threadIdx.x + p * 256;
            int rr = i / (K / 4), kk = i % (K / 4);
            float4 v = pre[p];
            if (RELU_IN) {
                v.x = fmaxf(v.x, 0.f); v.y = fmaxf(v.y, 0.f);
                v.z = fmaxf(v.z, 0.f); v.w = fmaxf(v.w, 0.f);
            }
            float di = pdi[p];
            __nv_bfloat162 lo = __floats2bfloat162_rn(v.x * di, v.y * di);
            __nv_bfloat162 hi = __floats2bfloat162_rn(v.z * di, v.w * di);
            uint2 u;
            u.x = *(unsigned*)&lo;
            u.y = *(unsigned*)&hi;
            *(uint2*)(Xs + rr * XSTR + kk * 4) = u;
        }
        __syncthreads();   // Xs ready

        // prefetch next tile's X while this tile computes
        int nxt = row0 + gridDim.x * ROWS;
        if (nxt < N_NODES) prefetch(nxt);

        // STRIPS independent accumulator chains, interleaved in the k-loop
        wmma::fragment<wmma::accumulator, 16, 16, 16, float> acc[STRIPS];
        #pragma unroll
        for (int st = 0; st < STRIPS; st++) wmma::fill_fragment(acc[st], 0.f);

        #pragma unroll
        for (int ks = 0; ks < KS; ks++) {
            #pragma unroll
            for (int st = 0; st < STRIPS; st++) {
                int rloc = (rg * STRIPS + st) * 16;
                wmma::fragment<wmma::matrix_a, 16, 16, 16, __nv_bfloat16,
                               wmma::row_major> a;
                wmma::load_matrix_sync(a, Xs + rloc * XSTR + ks * 16, XSTR);
                wmma::mma_sync(acc[st], a, bf[ks], acc[st]);
            }
        }

        #pragma unroll
        for (int st = 0; st < STRIPS; st++) {
            int rbase = row0 + (rg * STRIPS + st) * 16;
            if (rbase < N_NODES)   // N_NODES % 16 == 0 -> strip fully in-bounds
                wmma::store_matrix_sync(HS + (size_t)rbase * M + tile * 16,
                                        acc[st], M, wmma::mem_row_major);
        }
    }
}

// ---------------- aggregation: OUT[v] = dinv[v]*(sum_in HS[s] + HS[v]) + b ----
// x2 accumulator chains + index-prefetch pipeline (decouples the per-iteration
// seg[i] -> gather dependency; +2 int regs only, occupancy preserved).
template<int F>
__global__ void agg_gather(const float* __restrict__ HS, const float* __restrict__ bias,
                           float* __restrict__ OUT) {
    constexpr int TPN = F / 4;
    unsigned gid = blockIdx.x * blockDim.x + threadIdx.x;
    unsigned v = gid / TPN;
    if (v >= N_NODES) return;
    unsigned c = gid % TPN;
    const float4* hs = (const float4*)HS;

    const int* seg = g_srcs + (size_t)v * CAP;
    int cnt = __ldg(&g_cursor[v]);
    cnt = (cnt < CAP) ? cnt : CAP;

    float4 acc0 = __ldg(hs + (size_t)v * TPN + c);       // self-loop term
    float4 acc1 = make_float4(0.f, 0.f, 0.f, 0.f);

    int i = 0;
    if (cnt >= 2) {
        int s0 = __ldg(&seg[0]);
        int s1 = __ldg(&seg[1]);
        for (i = 2; i + 1 < cnt; i += 2) {
            int t0 = __ldg(&seg[i]);
            int t1 = __ldg(&seg[i + 1]);
            acc4(acc0, __ldg(hs + (size_t)s0 * TPN + c));
            acc4(acc1, __ldg(hs + (size_t)s1 * TPN + c));
            s0 = t0; s1 = t1;
        }
        acc4(acc0, __ldg(hs + (size_t)s0 * TPN + c));
        acc4(acc1, __ldg(hs + (size_t)s1 * TPN + c));
    }
    for (; i < cnt; i++) {
        int s = __ldg(&seg[i]);
        acc4(acc0, __ldg(hs + (size_t)s * TPN + c));
    }

    float di = __ldg(&g_dinv[v]);
    float4 bb = __ldg((const float4*)bias + c);
    float4 o;
    o.x = fmaf(acc0.x + acc1.x, di, bb.x);
    o.y = fmaf(acc0.y + acc1.y, di, bb.y);
    o.z = fmaf(acc0.z + acc1.z, di, bb.z);
    o.w = fmaf(acc0.w + acc1.w, di, bb.w);
    ((float4*)OUT)[(size_t)v * TPN + c] = o;
}

// ---------------- layer-3 aggregation fused with pooling (F=32) ----------------
__global__ void agg_pool(const float* __restrict__ HS, const float* __restrict__ bias,
                         const int* __restrict__ batch) {
    constexpr int TPN = 8;
    unsigned gid = blockIdx.x * blockDim.x + threadIdx.x;
    unsigned v = gid / TPN;
    if (v >= N_NODES) return;
    unsigned c = gid % TPN;
    const float4* hs = (const float4*)HS;

    const int* seg = g_srcs + (size_t)v * CAP;
    int cnt = __ldg(&g_cursor[v]);
    cnt = (cnt < CAP) ? cnt : CAP;

    float4 acc0 = __ldg(hs + (size_t)v * TPN + c);
    float4 acc1 = make_float4(0.f, 0.f, 0.f, 0.f);

    int i = 0;
    if (cnt >= 2) {
        int s0 = __ldg(&seg[0]);
        int s1 = __ldg(&seg[1]);
        for (i = 2; i + 1 < cnt; i += 2) {
            int t0 = __ldg(&seg[i]);
            int t1 = __ldg(&seg[i + 1]);
            acc4(acc0, __ldg(hs + (size_t)s0 * TPN + c));
            acc4(acc1, __ldg(hs + (size_t)s1 * TPN + c));
            s0 = t0; s1 = t1;
        }
        acc4(acc0, __ldg(hs + (size_t)s0 * TPN + c));
        acc4(acc1, __ldg(hs + (size_t)s1 * TPN + c));
    }
    for (; i < cnt; i++) {
        int s = __ldg(&seg[i]);
        acc4(acc0, __ldg(hs + (size_t)s * TPN + c));
    }

    float di = __ldg(&g_dinv[v]);
    float4 bb = __ldg((const float4*)bias + c);
    float4 o;
    o.x = fmaf(acc0.x + acc1.x, di, bb.x);
    o.y = fmaf(acc0.y + acc1.y, di, bb.y);
    o.z = fmaf(acc0.z + acc1.z, di, bb.z);
    o.w = fmaf(acc0.w + acc1.w, di, bb.w);

    int g = __ldg(&batch[v]);
    red_add_f32x4(&g_pool[g * 32 + c * 4], o);
}

// ---------------- head: counts via binary search on sorted batch ---------------
__device__ __forceinline__ int lower_bound_batch(const int* __restrict__ batch, int key) {
    int lo = 0, hi = N_NODES;
    while (lo < hi) {
        int mid = (lo + hi) >> 1;
        if (__ldg(&batch[mid]) < key) lo = mid + 1; else hi = mid;
    }
    return lo;
}

__global__ void head_kernel(const float* __restrict__ Wl, const float* __restrict__ bl,
                            const int* __restrict__ targets, const int* __restrict__ batch,
                            float* __restrict__ out, int out_size) {
    int g = blockIdx.x * blockDim.x + threadIdx.x;
    float loss = 0.f;
    if (g < N_GRAPHS) {
        int s0 = lower_bound_batch(batch, g);
        int s1 = lower_bound_batch(batch, g + 1);
        float cnt = (float)(s1 - s0);
        float inv = 1.0f / fmaxf(cnt, 1.0f);
        float acc = 0.f;
        #pragma unroll
        for (int j = 0; j < 32; j++)
            acc += g_pool[g * 32 + j] * inv * __ldg(&Wl[j]);
        float l = acc + __ldg(&bl[0]);
        out[g] = 1.0f / (1.0f + expf(-l));
        float y = (float)__ldg(&targets[g]);
        loss = fmaxf(l, 0.f) - l * y + log1pf(expf(-fabsf(l)));
    }
    __shared__ float red[256];
    red[threadIdx.x] = loss;
    __syncthreads();
    for (int s = 128; s > 0; s >>= 1) {
        if (threadIdx.x < s) red[threadIdx.x] += red[threadIdx.x + s];
        __syncthreads();
    }
    if (threadIdx.x == 0 && out_size > N_GRAPHS)
        atomicAdd(&out[N_GRAPHS], red[0] * (1.0f / N_GRAPHS));
}

// ---------------- launch ------------------------------------------------------
extern "C" void kernel_launch(void* const* d_in, const int* in_sizes, int n_in,
                              void* d_out, int out_size) {
    const float* x       = (const float*)d_in[0];
    const int*   eidx    = (const int*)  d_in[1];
    const int*   batch   = (const int*)  d_in[2];
    const int*   targets = (const int*)  d_in[3];
    const float* W1 = (const float*)d_in[4];
    const float* b1 = (const float*)d_in[5];
    const float* W2 = (const float*)d_in[6];
    const float* b2 = (const float*)d_in[7];
    const float* W3 = (const float*)d_in[8];
    const float* b3 = (const float*)d_in[9];
    const float* Wl = (const float*)d_in[10];
    const float* bl = (const float*)d_in[11];
    float* out = (float*)d_out;

    const int* src = eidx;
    const int* dst = eidx + N_EDGES;

    float* A;  cudaGetSymbolAddress((void**)&A, g_A);
    float* B;  cudaGetSymbolAddress((void**)&B, g_B);

    // bf16 smem: (K*M + ROWS*(K+16)) * 2 bytes
    const int smem1 = (128 * 128 + 32 * 144) * 2;  // 41984
    const int smem2 = (128 * 64  + 32 * 144) * 2;  // 25600
    const int smem3 = (64  * 32  + 64 * 80 ) * 2;  // 14336
    cudaFuncSetAttribute(gcn_gemm_tc<128,128,false,32>,
                         cudaFuncAttributeMaxDynamicSharedMemorySize, smem1);
    cudaFuncSetAttribute(gcn_gemm_tc<128,64,true,32>,
                         cudaFuncAttributeMaxDynamicSharedMemorySize, smem2);
    cudaFuncSetAttribute(gcn_gemm_tc<64,32,true,64>,
                         cudaFuncAttributeMaxDynamicSharedMemorySize, smem3);

    float* loss_slot = (out_size > N_GRAPHS) ? (out + N_GRAPHS) : nullptr;

    // ---- setup: zero -> fill (4 edges/thread) -> dinv
    zero_kernel<<<(N_NODES + 255) / 256, 256>>>(loss_slot);
    fill_kernel<<<(N_EDGES / 4 + 255) / 256, 256>>>(src, dst);
    dinv_kernel<<<(N_NODES + 255) / 256, 256>>>();

    // ---- layer 1: 128 -> 128   (gemm1 is launch #4 -> ncu window)
    gcn_gemm_tc<128,128,false,32><<<296, 256, smem1>>>(x, W1, A);
    agg_gather<128><<<((unsigned)N_NODES * 32 + 255) / 256, 256>>>(A, b1, B);
    // ---- layer 2: 128 -> 64 (relu on input)
    gcn_gemm_tc<128,64,true,32><<<296, 256, smem2>>>(B, W2, A);
    agg_gather<64><<<((unsigned)N_NODES * 16 + 255) / 256, 256>>>(A, b2, B);
    // ---- layer 3: 64 -> 32 (relu on input), aggregation fused with pooling
    gcn_gemm_tc<64,32,true,64><<<296, 256, smem3>>>(B, W3, A);
    agg_pool<<<((unsigned)N_NODES * 8 + 255) / 256, 256>>>(A, b3, batch);

    // ---- head
    head_kernel<<<(N_GRAPHS + 255) / 256, 256>>>(Wl, bl, targets, batch, out, out_size);
}